// round 1
// baseline (speedup 1.0000x reference)
#include <cuda_runtime.h>

// out = x^2 * 0.1, elementwise over 64*1024*1024 fp32.
// HBM-bound: 512 MiB total traffic. float4 vectorized, one element-quad per thread.

__global__ void poly_kernel_v4(const float4* __restrict__ x, float4* __restrict__ out, int n4) {
    int i = blockIdx.x * blockDim.x + threadIdx.x;
    if (i < n4) {
        float4 v = x[i];
        float4 r;
        r.x = v.x * v.x * 0.1f;
        r.y = v.y * v.y * 0.1f;
        r.z = v.z * v.z * 0.1f;
        r.w = v.w * v.w * 0.1f;
        out[i] = r;
    }
}

// Tail handler for n not divisible by 4 (not needed here, n = 64M, but safe).
__global__ void poly_kernel_tail(const float* __restrict__ x, float* __restrict__ out,
                                 int start, int n) {
    int i = start + blockIdx.x * blockDim.x + threadIdx.x;
    if (i < n) {
        float v = x[i];
        out[i] = v * v * 0.1f;
    }
}

extern "C" void kernel_launch(void* const* d_in, const int* in_sizes, int n_in,
                              void* d_out, int out_size) {
    const float* x = (const float*)d_in[0];
    float* out = (float*)d_out;
    int n = in_sizes[0];

    int n4 = n / 4;
    if (n4 > 0) {
        int threads = 256;
        int blocks = (n4 + threads - 1) / threads;
        poly_kernel_v4<<<blocks, threads>>>((const float4*)x, (float4*)out, n4);
    }
    int tail_start = n4 * 4;
    int tail = n - tail_start;
    if (tail > 0) {
        poly_kernel_tail<<<1, 32>>>(x, out, tail_start, n);
    }
}

// round 2
// speedup vs baseline: 1.0008x; 1.0008x over previous
#include <cuda_runtime.h>

// out = x^2 * 0.1 over 64M fp32. HBM-bound streaming kernel.
// v2: grid-stride, 4x float4 per thread with front-batched loads (MLP=4/thread),
//     streaming cache hints (__ldcs / __stcs) since data has zero reuse.

__global__ void __launch_bounds__(256) poly_kernel_v2(
    const float4* __restrict__ x, float4* __restrict__ out, int n4)
{
    const int stride = gridDim.x * blockDim.x;
    int i = blockIdx.x * blockDim.x + threadIdx.x;

    // Main path: 4 independent float4 loads in flight per thread.
    for (; i + 3 * stride < n4; i += 4 * stride) {
        float4 v0 = __ldcs(&x[i]);
        float4 v1 = __ldcs(&x[i + stride]);
        float4 v2 = __ldcs(&x[i + 2 * stride]);
        float4 v3 = __ldcs(&x[i + 3 * stride]);

        float4 r0, r1, r2, r3;
        r0.x = v0.x * v0.x * 0.1f; r0.y = v0.y * v0.y * 0.1f;
        r0.z = v0.z * v0.z * 0.1f; r0.w = v0.w * v0.w * 0.1f;
        r1.x = v1.x * v1.x * 0.1f; r1.y = v1.y * v1.y * 0.1f;
        r1.z = v1.z * v1.z * 0.1f; r1.w = v1.w * v1.w * 0.1f;
        r2.x = v2.x * v2.x * 0.1f; r2.y = v2.y * v2.y * 0.1f;
        r2.z = v2.z * v2.z * 0.1f; r2.w = v2.w * v2.w * 0.1f;
        r3.x = v3.x * v3.x * 0.1f; r3.y = v3.y * v3.y * 0.1f;
        r3.z = v3.z * v3.z * 0.1f; r3.w = v3.w * v3.w * 0.1f;

        __stcs(&out[i],              r0);
        __stcs(&out[i + stride],     r1);
        __stcs(&out[i + 2 * stride], r2);
        __stcs(&out[i + 3 * stride], r3);
    }
    // Remainder (n4 = 16M divisible in practice; kept for safety).
    for (; i < n4; i += stride) {
        float4 v = __ldcs(&x[i]);
        float4 r;
        r.x = v.x * v.x * 0.1f; r.y = v.y * v.y * 0.1f;
        r.z = v.z * v.z * 0.1f; r.w = v.w * v.w * 0.1f;
        __stcs(&out[i], r);
    }
}

__global__ void poly_kernel_tail(const float* __restrict__ x, float* __restrict__ out,
                                 int start, int n) {
    int i = start + blockIdx.x * blockDim.x + threadIdx.x;
    if (i < n) {
        float v = x[i];
        out[i] = v * v * 0.1f;
    }
}

extern "C" void kernel_launch(void* const* d_in, const int* in_sizes, int n_in,
                              void* d_out, int out_size) {
    const float* x = (const float*)d_in[0];
    float* out = (float*)d_out;
    int n = in_sizes[0];

    int n4 = n / 4;
    if (n4 > 0) {
        const int threads = 256;
        // 4 float4 per thread: total threads = n4/4.
        int blocks = (n4 / 4 + threads - 1) / threads;
        if (blocks < 1) blocks = 1;
        poly_kernel_v2<<<blocks, threads>>>((const float4*)x, (float4*)out, n4);
    }
    int tail_start = n4 * 4;
    if (n - tail_start > 0) {
        poly_kernel_tail<<<1, 32>>>(x, out, tail_start, n);
    }
}